// round 11
// baseline (speedup 1.0000x reference)
#include <cuda_runtime.h>
#include <cuda_fp16.h>

// Fisher-Kolmogorov rollout. R11 = R9 (fp32 state, z-pair MLP-10 body, PDL,
// fused fp16 {D,rho} prep) with CTA reshaped (32,8,4)=1024 thr: tile y=8,z=8,
// u-halo 1.875x -> 1.5625x. L2 traffic/step 54 -> 49 MB.

#define W        128
#define BATCH    2
#define SUBSTEPS 10
#define MAX_DAYS 4
#define NSTEPS   (SUBSTEPS * MAX_DAYS)
#define MICRO_DT 0.1f

#define VOL  ((size_t)W * W * W)
#define NTOT (BATCH * VOL)

__device__ float g_buf0[NTOT];
__device__ float g_buf1[NTOT];
__device__ __half2 g_dr[NTOT];          // {D, rho} per point (16 MB)

struct __align__(16) H24 { __half2 h[4]; };

__device__ __forceinline__ float4 f4ld(const float* p) {
    return *reinterpret_cast<const float4*>(p);
}

__device__ __forceinline__ void fk_comp(float& o, float c, float nb2,
                                        float nb4, __half2 drh)
{
    const float2 d2 = __half22float2(drh);        // x=D, y=rho
    const float lap = nb2 + nb4 - 6.0f * c;
    o = c + MICRO_DT * (d2.x * lap + d2.y * c * (1.0f - c));
}

__device__ __forceinline__ float4 fk_point(float4 c, float4 ym, float4 yp,
                                           float4 zm, float4 zp,
                                           float lf, float rt, H24 q)
{
    float4 o;
    fk_comp(o.x, c.x, lf  + c.y, ym.x + yp.x + zm.x + zp.x, q.h[0]);
    fk_comp(o.y, c.y, c.x + c.z, ym.y + yp.y + zm.y + zp.y, q.h[1]);
    fk_comp(o.z, c.z, c.y + c.w, ym.z + yp.z + zm.z + zp.z, q.h[2]);
    fk_comp(o.w, c.w, c.z + rt,  ym.w + yp.w + zm.w + zp.w, q.h[3]);
    return o;
}

__device__ __forceinline__ float4 clip01(float4 v)
{
    v.x = fminf(fmaxf(v.x, 0.f), 1.f);
    v.y = fminf(fmaxf(v.y, 0.f), 1.f);
    v.z = fminf(fmaxf(v.z, 0.f), 1.f);
    v.w = fminf(fmaxf(v.w, 0.f), 1.f);
    return v;
}

__device__ __forceinline__ H24 pack_dr(float4 d, float4 r)
{
    H24 q;
    q.h[0] = __floats2half2_rn(d.x, r.x);
    q.h[1] = __floats2half2_rn(d.y, r.y);
    q.h[2] = __floats2half2_rn(d.z, r.z);
    q.h[3] = __floats2half2_rn(d.w, r.w);
    return q;
}

// ---- step 0: reads fp32 D/rho, packs g_dr, computes micro-step 0 ----
__global__ __launch_bounds__(1024)
void fk_step0(const float* __restrict__ usrc,
              float* __restrict__ udst,
              const float* __restrict__ Dm,
              const float* __restrict__ Rm,
              __half2* __restrict__ dr,
              const int* __restrict__ dt_days)
{
#if __CUDA_ARCH__ >= 900
    cudaTriggerProgrammaticLaunchCompletion();
#endif
    const int b  = blockIdx.z;
    const int dt = __ldg(dt_days + b);
    if (dt <= 0) return;                 // step 0 (day 0) is never "fin"

    const int tx = threadIdx.x;
    const int y  = blockIdx.y * 8 + threadIdx.y;
    const int z0 = (blockIdx.x * 4 + threadIdx.z) * 2;
    const int x4 = tx << 2;

    const size_t PL = (size_t)W * W;
    const size_t base = ((size_t)b * VOL) + (((size_t)z0 * W) + y) * W + x4;

    const float4 zero4 = make_float4(0.f, 0.f, 0.f, 0.f);

    const float4 um  = (z0 > 0)     ? f4ld(usrc + base - PL)     : zero4;
    const float4 u0  =                f4ld(usrc + base);
    const float4 u1  =                f4ld(usrc + base + PL);
    const float4 up  = (z0 < W - 2) ? f4ld(usrc + base + 2 * PL) : zero4;
    const float4 ym0 = (y > 0)      ? f4ld(usrc + base - W)      : zero4;
    const float4 yp0 = (y < W - 1)  ? f4ld(usrc + base + W)      : zero4;
    const float4 ym1 = (y > 0)      ? f4ld(usrc + base + PL - W) : zero4;
    const float4 yp1 = (y < W - 1)  ? f4ld(usrc + base + PL + W) : zero4;
    const float4 d0  = f4ld(Dm + base);
    const float4 r0  = f4ld(Rm + base);
    const float4 d1  = f4ld(Dm + base + PL);
    const float4 r1  = f4ld(Rm + base + PL);

    const H24 q0 = pack_dr(d0, r0);
    const H24 q1 = pack_dr(d1, r1);
    *reinterpret_cast<H24*>(dr + base)      = q0;
    *reinterpret_cast<H24*>(dr + base + PL) = q1;

    float lf0 = __shfl_up_sync(0xffffffffu, u0.w, 1);
    float rt0 = __shfl_down_sync(0xffffffffu, u0.x, 1);
    float lf1 = __shfl_up_sync(0xffffffffu, u1.w, 1);
    float rt1 = __shfl_down_sync(0xffffffffu, u1.x, 1);
    if (tx == 0)  { lf0 = 0.f; lf1 = 0.f; }
    if (tx == 31) { rt0 = 0.f; rt1 = 0.f; }

    const float4 o0 = fk_point(u0, ym0, yp0, um, u1, lf0, rt0, q0);
    const float4 o1 = fk_point(u1, ym1, yp1, u0, up, lf1, rt1, q1);

    *reinterpret_cast<float4*>(udst + base)      = o0;
    *reinterpret_cast<float4*>(udst + base + PL) = o1;
}

// ---- steps 1..39: fp32 state, fp16 dr; finishing step writes d_out ----
__global__ __launch_bounds__(1024)
void fk_step(const float* __restrict__ usrc,
             float* __restrict__ udst,
             float* __restrict__ uout,
             const __half2* __restrict__ dr,
             const int* __restrict__ dt_days,
             int day, int sub)
{
#if __CUDA_ARCH__ >= 900
    cudaTriggerProgrammaticLaunchCompletion();
#endif
    const int b  = blockIdx.z;
    const int dt = __ldg(dt_days + b);   // never written by any kernel
    if (day >= dt) return;                // inactive: fully overlapped via PDL
    const bool fin = (day == dt - 1) && (sub == SUBSTEPS - 1);

    const int tx = threadIdx.x;
    const int y  = blockIdx.y * 8 + threadIdx.y;
    const int z0 = (blockIdx.x * 4 + threadIdx.z) * 2;
    const int x4 = tx << 2;

    const size_t PL = (size_t)W * W;
    const size_t base = ((size_t)b * VOL) + (((size_t)z0 * W) + y) * W + x4;

#if __CUDA_ARCH__ >= 900
    cudaGridDependencySynchronize();
#endif

    const float4 zero4 = make_float4(0.f, 0.f, 0.f, 0.f);

    // 10 independent vector loads (MLP ~ 10)
    const float4 um  = (z0 > 0)     ? f4ld(usrc + base - PL)     : zero4;
    const float4 u0  =                f4ld(usrc + base);
    const float4 u1  =                f4ld(usrc + base + PL);
    const float4 up  = (z0 < W - 2) ? f4ld(usrc + base + 2 * PL) : zero4;
    const float4 ym0 = (y > 0)      ? f4ld(usrc + base - W)      : zero4;
    const float4 yp0 = (y < W - 1)  ? f4ld(usrc + base + W)      : zero4;
    const float4 ym1 = (y > 0)      ? f4ld(usrc + base + PL - W) : zero4;
    const float4 yp1 = (y < W - 1)  ? f4ld(usrc + base + PL + W) : zero4;
    const H24 q0 = *reinterpret_cast<const H24*>(dr + base);
    const H24 q1 = *reinterpret_cast<const H24*>(dr + base + PL);

    float lf0 = __shfl_up_sync(0xffffffffu, u0.w, 1);
    float rt0 = __shfl_down_sync(0xffffffffu, u0.x, 1);
    float lf1 = __shfl_up_sync(0xffffffffu, u1.w, 1);
    float rt1 = __shfl_down_sync(0xffffffffu, u1.x, 1);
    if (tx == 0)  { lf0 = 0.f; lf1 = 0.f; }
    if (tx == 31) { rt0 = 0.f; rt1 = 0.f; }

    float4 o0 = fk_point(u0, ym0, yp0, um, u1, lf0, rt0, q0);
    float4 o1 = fk_point(u1, ym1, yp1, u0, up, lf1, rt1, q1);

    if (fin) {
        o0 = clip01(o0);
        o1 = clip01(o1);
        *reinterpret_cast<float4*>(uout + base)      = o0;
        *reinterpret_cast<float4*>(uout + base + PL) = o1;
    } else {
        *reinterpret_cast<float4*>(udst + base)      = o0;
        *reinterpret_cast<float4*>(udst + base + PL) = o1;
    }
}

// dt==0 batches: clipped copy of u_t0 -> d_out (independent; no gridsync).
__global__ __launch_bounds__(512)
void fk_tail(const float* __restrict__ u0,
             float* __restrict__ out,
             const int* __restrict__ dt_days)
{
#if __CUDA_ARCH__ >= 900
    cudaTriggerProgrammaticLaunchCompletion();
#endif
    const int b = blockIdx.z >> 5;
    if (__ldg(dt_days + b) != 0) return;

    const int x4 = threadIdx.x << 2;
    const int y  = blockIdx.y * 4 + threadIdx.y;
    const int z  = (blockIdx.z & 31) * 4 + threadIdx.z;
    const size_t base = (((size_t)b * W + z) * W + y) * W + x4;

    float4 v = f4ld(u0 + base);
    *reinterpret_cast<float4*>(out + base) = clip01(v);
}

extern "C" void kernel_launch(void* const* d_in, const int* in_sizes, int n_in,
                              void* d_out, int out_size)
{
    const float* u_t0    = (const float*)d_in[0];
    const float* D_map   = (const float*)d_in[1];
    const float* rho_map = (const float*)d_in[2];
    const int*   dt_days = (const int*)  d_in[3];
    float*       out     = (float*)d_out;

    float *p0 = nullptr, *p1 = nullptr;
    __half2* dr = nullptr;
    cudaGetSymbolAddress((void**)&p0, g_buf0);
    cudaGetSymbolAddress((void**)&p1, g_buf1);
    cudaGetSymbolAddress((void**)&dr, g_dr);
    float* bufs[2] = { p0, p1 };

    dim3 block(32, 8, 4);                        // 1024 threads
    dim3 grid(W / 8, W / 8, BATCH);              // (16, 16, 2) = 512 blocks

    cudaLaunchAttribute attrs[1];
    attrs[0].id = cudaLaunchAttributeProgrammaticStreamSerialization;
    attrs[0].val.programmaticStreamSerializationAllowed = 1;

    cudaLaunchConfig_t cfg = {};
    cfg.gridDim = grid;
    cfg.blockDim = block;
    cfg.dynamicSmemBytes = 0;
    cfg.stream = 0;
    cfg.attrs = attrs;
    cfg.numAttrs = 1;

    // Step 0: fused fp16 packing + first micro-step.
    cudaLaunchKernelEx(&cfg, fk_step0, u_t0, bufs[1], D_map, rho_map,
                       (__half2*)dr, dt_days);

    // Steps 1..39 (ping-pong; step s reads bufs[s&1], writes bufs[(s+1)&1]).
    for (int s = 1; s < NSTEPS; ++s) {
        const float* src = bufs[s & 1];
        float*       dst = bufs[(s + 1) & 1];
        cudaLaunchKernelEx(&cfg, fk_step, src, dst, out,
                           (const __half2*)dr, dt_days,
                           s / SUBSTEPS, s % SUBSTEPS);
    }

    // Tail for dt==0 batches (fully overlappable).
    cudaLaunchConfig_t tcfg = cfg;
    tcfg.gridDim = dim3(1, W / 4, (W / 4) * BATCH);
    tcfg.blockDim = dim3(32, 4, 4);
    cudaLaunchKernelEx(&tcfg, fk_tail, u_t0, out, dt_days);

    (void)in_sizes; (void)n_in; (void)out_size;
}

// round 12
// speedup vs baseline: 1.2097x; 1.2097x over previous
#include <cuda_runtime.h>
#include <cuda_fp16.h>

// Fisher-Kolmogorov rollout. R12: tile y=8,z=8 (halo 1.5625x, 49 MB/step)
// with 512-thread CTAs — block (32,8,2), 4 z-points per thread computed as
// two register-shifted z-pair iterations. PDL + fused fp16 {D,rho} prep.

#define W        128
#define BATCH    2
#define SUBSTEPS 10
#define MAX_DAYS 4
#define NSTEPS   (SUBSTEPS * MAX_DAYS)
#define MICRO_DT 0.1f

#define VOL  ((size_t)W * W * W)
#define NTOT (BATCH * VOL)

__device__ float g_buf0[NTOT];
__device__ float g_buf1[NTOT];
__device__ __half2 g_dr[NTOT];          // {D, rho} per point (16 MB)

struct __align__(16) H24 { __half2 h[4]; };

__device__ __forceinline__ float4 f4ld(const float* p) {
    return *reinterpret_cast<const float4*>(p);
}

__device__ __forceinline__ void fk_comp(float& o, float c, float nb2,
                                        float nb4, __half2 drh)
{
    const float2 d2 = __half22float2(drh);        // x=D, y=rho
    const float lap = nb2 + nb4 - 6.0f * c;
    o = c + MICRO_DT * (d2.x * lap + d2.y * c * (1.0f - c));
}

__device__ __forceinline__ float4 fk_point(float4 c, float4 ym, float4 yp,
                                           float4 zm, float4 zp,
                                           float lf, float rt, H24 q)
{
    float4 o;
    fk_comp(o.x, c.x, lf  + c.y, ym.x + yp.x + zm.x + zp.x, q.h[0]);
    fk_comp(o.y, c.y, c.x + c.z, ym.y + yp.y + zm.y + zp.y, q.h[1]);
    fk_comp(o.z, c.z, c.y + c.w, ym.z + yp.z + zm.z + zp.z, q.h[2]);
    fk_comp(o.w, c.w, c.z + rt,  ym.w + yp.w + zm.w + zp.w, q.h[3]);
    return o;
}

__device__ __forceinline__ float4 clip01(float4 v)
{
    v.x = fminf(fmaxf(v.x, 0.f), 1.f);
    v.y = fminf(fmaxf(v.y, 0.f), 1.f);
    v.z = fminf(fmaxf(v.z, 0.f), 1.f);
    v.w = fminf(fmaxf(v.w, 0.f), 1.f);
    return v;
}

__device__ __forceinline__ H24 pack_dr(float4 d, float4 r)
{
    H24 q;
    q.h[0] = __floats2half2_rn(d.x, r.x);
    q.h[1] = __floats2half2_rn(d.y, r.y);
    q.h[2] = __floats2half2_rn(d.z, r.z);
    q.h[3] = __floats2half2_rn(d.w, r.w);
    return q;
}

// x-halo via warp shuffles for one plane
__device__ __forceinline__ void xhalo(float4 u, int tx, float& lf, float& rt)
{
    lf = __shfl_up_sync(0xffffffffu, u.w, 1);
    rt = __shfl_down_sync(0xffffffffu, u.x, 1);
    if (tx == 0)  lf = 0.f;
    if (tx == 31) rt = 0.f;
}

// ---- step 0 (R9 geometry): fp32 in, pack g_dr, micro-step 0 ----
__global__ __launch_bounds__(512)
void fk_step0(const float* __restrict__ usrc,
              float* __restrict__ udst,
              const float* __restrict__ Dm,
              const float* __restrict__ Rm,
              __half2* __restrict__ dr,
              const int* __restrict__ dt_days)
{
#if __CUDA_ARCH__ >= 900
    cudaTriggerProgrammaticLaunchCompletion();
#endif
    const int b  = blockIdx.z;
    const int dt = __ldg(dt_days + b);
    if (dt <= 0) return;                 // step 0 (day 0) is never "fin"

    const int tx = threadIdx.x;
    const int y  = blockIdx.y * 4 + threadIdx.y;
    const int z0 = (blockIdx.x * 4 + threadIdx.z) * 2;
    const int x4 = tx << 2;

    const size_t PL = (size_t)W * W;
    const size_t base = ((size_t)b * VOL) + (((size_t)z0 * W) + y) * W + x4;

    const float4 zero4 = make_float4(0.f, 0.f, 0.f, 0.f);

    const float4 um  = (z0 > 0)     ? f4ld(usrc + base - PL)     : zero4;
    const float4 u0  =                f4ld(usrc + base);
    const float4 u1  =                f4ld(usrc + base + PL);
    const float4 up  = (z0 < W - 2) ? f4ld(usrc + base + 2 * PL) : zero4;
    const float4 ym0 = (y > 0)      ? f4ld(usrc + base - W)      : zero4;
    const float4 yp0 = (y < W - 1)  ? f4ld(usrc + base + W)      : zero4;
    const float4 ym1 = (y > 0)      ? f4ld(usrc + base + PL - W) : zero4;
    const float4 yp1 = (y < W - 1)  ? f4ld(usrc + base + PL + W) : zero4;
    const float4 d0  = f4ld(Dm + base);
    const float4 r0  = f4ld(Rm + base);
    const float4 d1  = f4ld(Dm + base + PL);
    const float4 r1  = f4ld(Rm + base + PL);

    const H24 q0 = pack_dr(d0, r0);
    const H24 q1 = pack_dr(d1, r1);
    *reinterpret_cast<H24*>(dr + base)      = q0;
    *reinterpret_cast<H24*>(dr + base + PL) = q1;

    float lf0, rt0, lf1, rt1;
    xhalo(u0, tx, lf0, rt0);
    xhalo(u1, tx, lf1, rt1);

    const float4 o0 = fk_point(u0, ym0, yp0, um, u1, lf0, rt0, q0);
    const float4 o1 = fk_point(u1, ym1, yp1, u0, up, lf1, rt1, q1);

    *reinterpret_cast<float4*>(udst + base)      = o0;
    *reinterpret_cast<float4*>(udst + base + PL) = o1;
}

// ---- steps 1..39: block (32,8,2); 4 z-points/thread in 2 sub-iterations ----
__global__ __launch_bounds__(512, 2)
void fk_step(const float* __restrict__ usrc,
             float* __restrict__ udst,
             float* __restrict__ uout,
             const __half2* __restrict__ dr,
             const int* __restrict__ dt_days,
             int day, int sub)
{
#if __CUDA_ARCH__ >= 900
    cudaTriggerProgrammaticLaunchCompletion();
#endif
    const int b  = blockIdx.z;
    const int dt = __ldg(dt_days + b);   // never written by any kernel
    if (day >= dt) return;                // inactive: fully overlapped via PDL
    const bool fin = (day == dt - 1) && (sub == SUBSTEPS - 1);

    const int tx = threadIdx.x;
    const int y  = blockIdx.y * 8 + threadIdx.y;        // tile y = 8
    const int zb = blockIdx.x * 8 + threadIdx.z * 4;    // tile z = 8; 4 z/thread
    const int x4 = tx << 2;

    const size_t PL = (size_t)W * W;
    const size_t base = ((size_t)b * VOL) + (((size_t)zb * W) + y) * W + x4;

#if __CUDA_ARCH__ >= 900
    cudaGridDependencySynchronize();
#endif

    const float4 zero4 = make_float4(0.f, 0.f, 0.f, 0.f);
    const bool ylo = (y > 0), yhi = (y < W - 1);

    // ---- sub-iteration 0: outputs zb, zb+1 (planes zb-1 .. zb+2) ----
    // zb ranges over {0,4,...,124}: zb+2 <= 126 and zb+3 <= 127 always valid.
    float4 um = (zb > 0) ? f4ld(usrc + base - PL) : zero4;
    float4 u0 = f4ld(usrc + base);
    float4 u1 = f4ld(usrc + base + PL);
    float4 u2 = f4ld(usrc + base + 2 * PL);
    float4 ym0 = ylo ? f4ld(usrc + base - W)      : zero4;
    float4 yp0 = yhi ? f4ld(usrc + base + W)      : zero4;
    float4 ym1 = ylo ? f4ld(usrc + base + PL - W) : zero4;
    float4 yp1 = yhi ? f4ld(usrc + base + PL + W) : zero4;
    H24 q0 = *reinterpret_cast<const H24*>(dr + base);
    H24 q1 = *reinterpret_cast<const H24*>(dr + base + PL);

    float lf0, rt0, lf1, rt1;
    xhalo(u0, tx, lf0, rt0);
    xhalo(u1, tx, lf1, rt1);

    float4 o0 = fk_point(u0, ym0, yp0, um, u1, lf0, rt0, q0);
    float4 o1 = fk_point(u1, ym1, yp1, u0, u2, lf1, rt1, q1);

    // ---- sub-iteration 1: outputs zb+2, zb+3 (planes zb+1 .. zb+4) ----
    float4 u3 = f4ld(usrc + base + 3 * PL);
    float4 u4 = (zb + 4 < W) ? f4ld(usrc + base + 4 * PL) : zero4;
    float4 ym2 = ylo ? f4ld(usrc + base + 2 * PL - W) : zero4;
    float4 yp2 = yhi ? f4ld(usrc + base + 2 * PL + W) : zero4;
    float4 ym3 = ylo ? f4ld(usrc + base + 3 * PL - W) : zero4;
    float4 yp3 = yhi ? f4ld(usrc + base + 3 * PL + W) : zero4;
    H24 q2 = *reinterpret_cast<const H24*>(dr + base + 2 * PL);
    H24 q3 = *reinterpret_cast<const H24*>(dr + base + 3 * PL);

    float lf2, rt2, lf3, rt3;
    xhalo(u2, tx, lf2, rt2);
    xhalo(u3, tx, lf3, rt3);

    float4 o2 = fk_point(u2, ym2, yp2, u1, u3, lf2, rt2, q2);
    float4 o3 = fk_point(u3, ym3, yp3, u2, u4, lf3, rt3, q3);

    if (fin) {
        *reinterpret_cast<float4*>(uout + base)          = clip01(o0);
        *reinterpret_cast<float4*>(uout + base + PL)     = clip01(o1);
        *reinterpret_cast<float4*>(uout + base + 2 * PL) = clip01(o2);
        *reinterpret_cast<float4*>(uout + base + 3 * PL) = clip01(o3);
    } else {
        *reinterpret_cast<float4*>(udst + base)          = o0;
        *reinterpret_cast<float4*>(udst + base + PL)     = o1;
        *reinterpret_cast<float4*>(udst + base + 2 * PL) = o2;
        *reinterpret_cast<float4*>(udst + base + 3 * PL) = o3;
    }
}

// dt==0 batches: clipped copy of u_t0 -> d_out (independent; no gridsync).
__global__ __launch_bounds__(512)
void fk_tail(const float* __restrict__ u0,
             float* __restrict__ out,
             const int* __restrict__ dt_days)
{
#if __CUDA_ARCH__ >= 900
    cudaTriggerProgrammaticLaunchCompletion();
#endif
    const int b = blockIdx.z >> 5;
    if (__ldg(dt_days + b) != 0) return;

    const int x4 = threadIdx.x << 2;
    const int y  = blockIdx.y * 4 + threadIdx.y;
    const int z  = (blockIdx.z & 31) * 4 + threadIdx.z;
    const size_t base = (((size_t)b * W + z) * W + y) * W + x4;

    float4 v = f4ld(u0 + base);
    *reinterpret_cast<float4*>(out + base) = clip01(v);
}

extern "C" void kernel_launch(void* const* d_in, const int* in_sizes, int n_in,
                              void* d_out, int out_size)
{
    const float* u_t0    = (const float*)d_in[0];
    const float* D_map   = (const float*)d_in[1];
    const float* rho_map = (const float*)d_in[2];
    const int*   dt_days = (const int*)  d_in[3];
    float*       out     = (float*)d_out;

    float *p0 = nullptr, *p1 = nullptr;
    __half2* dr = nullptr;
    cudaGetSymbolAddress((void**)&p0, g_buf0);
    cudaGetSymbolAddress((void**)&p1, g_buf1);
    cudaGetSymbolAddress((void**)&dr, g_dr);
    float* bufs[2] = { p0, p1 };

    cudaLaunchAttribute attrs[1];
    attrs[0].id = cudaLaunchAttributeProgrammaticStreamSerialization;
    attrs[0].val.programmaticStreamSerializationAllowed = 1;

    // Step 0 config (R9 geometry).
    cudaLaunchConfig_t cfg0 = {};
    cfg0.gridDim = dim3(W / 8, W / 4, BATCH);     // (16, 32, 2)
    cfg0.blockDim = dim3(32, 4, 4);
    cfg0.stream = 0;
    cfg0.attrs = attrs;
    cfg0.numAttrs = 1;

    // Steps 1..39 config (y=8, z=8 tiles).
    cudaLaunchConfig_t cfg = cfg0;
    cfg.gridDim = dim3(W / 8, W / 8, BATCH);      // (16, 16, 2) = 512 blocks
    cfg.blockDim = dim3(32, 8, 2);                // 512 threads

    // Step 0: fused fp16 packing + first micro-step.
    cudaLaunchKernelEx(&cfg0, fk_step0, u_t0, bufs[1], D_map, rho_map,
                       (__half2*)dr, dt_days);

    // Steps 1..39 (ping-pong; step s reads bufs[s&1], writes bufs[(s+1)&1]).
    for (int s = 1; s < NSTEPS; ++s) {
        const float* src = bufs[s & 1];
        float*       dst = bufs[(s + 1) & 1];
        cudaLaunchKernelEx(&cfg, fk_step, src, dst, out,
                           (const __half2*)dr, dt_days,
                           s / SUBSTEPS, s % SUBSTEPS);
    }

    // Tail for dt==0 batches (fully overlappable).
    cudaLaunchConfig_t tcfg = cfg0;
    tcfg.gridDim = dim3(1, W / 4, (W / 4) * BATCH);
    tcfg.blockDim = dim3(32, 4, 4);
    cudaLaunchKernelEx(&tcfg, fk_tail, u_t0, out, dt_days);

    (void)in_sizes; (void)n_in; (void)out_size;
}